// round 16
// baseline (speedup 1.0000x reference)
#include <cuda_runtime.h>
#include <cuda_fp16.h>
#include <cstdint>
#include <cstring>

#define NN 100000
#define NE 1600000
#define D  128
#define NL 3
#define NB_SCAN ((NN + 1023) / 1024)   // 98
#define NTILES ((NN + 127) / 128)      // 782

// Scratch (allocation-free rule: __device__ globals). Activations fp16:
// row = 128 halfs = 256B = 16 uint4.
__device__ __align__(16) uint4 g_xa[(size_t)NN * 16];
__device__ __align__(16) uint4 g_xb[(size_t)NN * 16];
__device__ __align__(16) uint4 g_h [(size_t)NN * 16];
__device__ __align__(16) uint2 g_w16[(size_t)NL * 2 * 4096]; // fp16 weight images
__device__ int g_deg[NN];
__device__ int g_rows[NN];
__device__ int g_rowend[NN];
__device__ int g_cursor[NN];
__device__ int g_srcs[NE];
__device__ int g_misc[4];              // [0..2]: tile ctrs, [3]: scan allocator

// ---------------------------------------------------------------------------
// smem layout for MLP kernel (bytes). WST=136 halfs -> conflict-free ldmatrix.
// Single-term fp16 weights (measured error: ~7.0e-4 total; frozen).
// ---------------------------------------------------------------------------
#define WST 136
#define WSZ (128 * WST * 2)            // 34816 B per 128x128 fp16 image
#define OFF_W1  0
#define OFF_W2  (OFF_W1 + WSZ)
#define OFF_A   (OFF_W2 + WSZ)
#define OFF_BS1 (OFF_A + WSZ)          // 128 floats
#define OFF_BS2 (OFF_BS1 + 512)
#define SMEM_TOT (OFF_BS2 + 512)       // 105472 B

// ---------------------------------------------------------------------------
// helpers
// ---------------------------------------------------------------------------
__device__ __forceinline__ uint32_t smem_u32(const void* p) {
    uint32_t a;
    asm("{ .reg .u64 t; cvta.to.shared.u64 t, %1; cvt.u32.u64 %0, t; }"
        : "=r"(a) : "l"(p));
    return a;
}
__device__ __forceinline__ uint32_t packh2(float a, float b) {
    __half2 p = __floats2half2_rn(a, b);
    uint32_t r;
    memcpy(&r, &p, 4);
    return r;
}
__device__ __forceinline__ void ldsm4(uint32_t* r, uint32_t addr) {
    asm volatile("ldmatrix.sync.aligned.m8n8.x4.shared.b16 {%0,%1,%2,%3}, [%4];"
                 : "=r"(r[0]), "=r"(r[1]), "=r"(r[2]), "=r"(r[3]) : "r"(addr));
}
__device__ __forceinline__ void ldsm4t(uint32_t* r, uint32_t addr) {
    asm volatile("ldmatrix.sync.aligned.m8n8.x4.trans.shared.b16 {%0,%1,%2,%3}, [%4];"
                 : "=r"(r[0]), "=r"(r[1]), "=r"(r[2]), "=r"(r[3]) : "r"(addr));
}
__device__ __forceinline__ void mma_f16(float* c, const uint32_t* a,
                                        const uint32_t* b) {
    asm volatile("mma.sync.aligned.m16n8k16.row.col.f32.f16.f16.f32 "
                 "{%0,%1,%2,%3}, {%4,%5,%6,%7}, {%8,%9}, {%0,%1,%2,%3};"
                 : "+f"(c[0]), "+f"(c[1]), "+f"(c[2]), "+f"(c[3])
                 : "r"(a[0]), "r"(a[1]), "r"(a[2]), "r"(a[3]),
                   "r"(b[0]), "r"(b[1]));
}

// ---------------------------------------------------------------------------
// hist + x->fp16 + weight->fp16 conversion (fused single pass)
// ---------------------------------------------------------------------------
__global__ void hist_cvt_kernel(const int* __restrict__ dst, int* __restrict__ deg,
                                const float4* __restrict__ x, uint2* __restrict__ o,
                                const float4* __restrict__ W1,
                                const float4* __restrict__ W2,
                                uint2* __restrict__ w16) {
    int i = blockIdx.x * blockDim.x + threadIdx.x;
    if (i < NE) atomicAdd(&deg[__ldg(dst + i)], 1);
    int stride = gridDim.x * blockDim.x;
    for (int j = i; j < NN * 32; j += stride) {
        float4 v = __ldg(x + j);
        o[j] = make_uint2(packh2(v.x, v.y), packh2(v.z, v.w));
    }
    for (int j = i; j < NL * 2 * 4096; j += stride) {
        float4 v = (j < NL * 4096) ? __ldg(W1 + j) : __ldg(W2 + (j - NL * 4096));
        w16[j] = make_uint2(packh2(v.x, v.y), packh2(v.z, v.w));
    }
}

// ---------------------------------------------------------------------------
// fused scan: per-block exclusive scan + atomic block allocation.
// ---------------------------------------------------------------------------
__global__ void scan_kernel(const int* __restrict__ deg, int* __restrict__ rows,
                            int* __restrict__ rowend, int* __restrict__ cursor,
                            int* __restrict__ alloc) {
    __shared__ int ts[256];
    __shared__ int s_base;
    const int t = threadIdx.x;
    const int base = blockIdx.x * 1024 + t * 4;
    int v[4], s = 0;
    #pragma unroll
    for (int i = 0; i < 4; i++) {
        v[i] = (base + i < NN) ? deg[base + i] : 0;
        s += v[i];
    }
    ts[t] = s;
    __syncthreads();
    #pragma unroll
    for (int off = 1; off < 256; off <<= 1) {
        int x = (t >= off) ? ts[t - off] : 0;
        __syncthreads();
        ts[t] += x;
        __syncthreads();
    }
    if (t == 255) s_base = atomicAdd(alloc, ts[255]);
    __syncthreads();
    int run = s_base + ts[t] - s;
    #pragma unroll
    for (int i = 0; i < 4; i++) {
        if (base + i < NN) {
            rows[base + i] = run;
            cursor[base + i] = run;
            rowend[base + i] = run + v[i];
        }
        run += v[i];
    }
}

__global__ void fill_kernel(const int* __restrict__ src, const int* __restrict__ dst,
                            int* __restrict__ cursor, int* __restrict__ srcs) {
    int i = blockIdx.x * blockDim.x + threadIdx.x;
    if (i < NE) {
        int d = __ldg(dst + i);
        int pos = atomicAdd(&cursor[d], 1);
        srcs[pos] = __ldg(src + i);
    }
}

// ---------------------------------------------------------------------------
// tensor-core gather: one 64-thread block (2 warps) per node.
// Virtual edges = [self] + neighbors, processed in 16-row blocks:
//   stage rows into smem tile (16 x 272B, zero-padded), then
//   D += ones(16x16) @ B(16x128) via mma.sync — sum lands in fp32 accumulators
//   with NO per-element cvt/FADD. All D rows identical; lanes 0-3 hold row 0.
// Warp w owns features [w*64, w*64+64).
// ---------------------------------------------------------------------------
__global__ __launch_bounds__(64)
void gather_mma_kernel(const uint4* __restrict__ x, const int* __restrict__ rows,
                       const int* __restrict__ rowend, const int* __restrict__ srcs,
                       uint4* __restrict__ h) {
    __shared__ __align__(16) char tile[16 * 272];
    const int n = blockIdx.x;
    const int tid = threadIdx.x;
    const int wid = tid >> 5;
    const int lane = tid & 31;
    const int half = lane >> 4;
    const int sub = lane & 15;
    const uint32_t tb = smem_u32(tile);

    const int r0 = __ldg(rows + n);
    const int total = __ldg(rowend + n) - r0 + 1;    // + self (vidx 0)
    const int nblk = (total + 15) >> 4;

    float c[8][4];
    #pragma unroll
    for (int m = 0; m < 8; m++)
        #pragma unroll
        for (int q = 0; q < 4; q++) c[m][q] = 0.f;

    const uint32_t af[4] = {0x3C003C00u, 0x3C003C00u, 0x3C003C00u, 0x3C003C00u};
    const int arow = lane & 15;
    const int asel = half * 8;

    for (int b = 0; b < nblk; b++) {
        // stage: warp wid stages rows wid*8 .. wid*8+7 (half-warp per row)
        #pragma unroll
        for (int i = 0; i < 4; i++) {
            int row = wid * 8 + i * 2 + half;
            int vidx = b * 16 + row;
            uint4 p = make_uint4(0u, 0u, 0u, 0u);
            if (vidx < total) {
                int g = (vidx == 0) ? n : __ldg(srcs + r0 + vidx - 1);
                p = __ldg(x + (size_t)g * 16 + sub);
            }
            *(uint4*)(tile + row * 272 + sub * 16) = p;
        }
        __syncthreads();
        #pragma unroll
        for (int fg = 0; fg < 4; fg++) {
            uint32_t bf[4];
            ldsm4t(bf, tb + (uint32_t)(arow * WST + wid * 64 + fg * 16 + asel) * 2);
            mma_f16(c[fg * 2],     af, &bf[0]);
            mma_f16(c[fg * 2 + 1], af, &bf[2]);
        }
        __syncthreads();
    }

    // epilogue: lanes 0-3 (row group 0) write the warp's 64 features
    if (lane < 4) {
        uint32_t* o16 = (uint32_t*)h;
        #pragma unroll
        for (int m = 0; m < 8; m++) {
            int off32 = wid * 32 + (m >> 1) * 8 + (m & 1) * 4 + lane;
            o16[(size_t)n * 64 + off32] = packh2(c[m][0], c[m][1]);
        }
    }
}

// ---------------------------------------------------------------------------
// persistent tensor-core MLP: out = [relu]( relu(h @ W1 + b1) @ W2 + b2 )
// fp16 A, single-term fp16 weights (pre-converted images), fp32 accumulate.
// ---------------------------------------------------------------------------
__global__ __launch_bounds__(512, 1)
void mlp_mma_kernel(const uint4* __restrict__ hin,
                    const uint2* __restrict__ w1img, const float* __restrict__ b1,
                    const uint2* __restrict__ w2img, const float* __restrict__ b2,
                    void* __restrict__ outp, int inter, int* __restrict__ ctr) {
    extern __shared__ char smem[];
    const uint32_t sb = smem_u32(smem);
    const int tid  = threadIdx.x;
    const int lane = tid & 31;
    const int wid  = tid >> 5;
    const int wm   = wid >> 2;
    const int wn   = wid & 3;
    __shared__ int s_tile;

    for (int i = tid; i < 4096; i += 512) {
        int k = i >> 5, c4 = (i & 31) * 4;
        uint32_t doff = (uint32_t)(k * WST + c4) * 2;
        *(uint2*)(smem + OFF_W1 + doff) = __ldg(w1img + k * 32 + (i & 31));
        *(uint2*)(smem + OFF_W2 + doff) = __ldg(w2img + k * 32 + (i & 31));
    }
    if (tid < D) {
        ((float*)(smem + OFF_BS1))[tid] = __ldg(b1 + tid);
        ((float*)(smem + OFF_BS2))[tid] = __ldg(b2 + tid);
    }

    const float* bs1f = (const float*)(smem + OFF_BS1);
    const float* bs2f = (const float*)(smem + OFF_BS2);
    const int tg = lane >> 2;
    const int t4 = lane & 3;

    float c[2][4][4];

    auto gemm = [&](uint32_t woff) {
        #pragma unroll
        for (int mt = 0; mt < 2; mt++)
            #pragma unroll
            for (int ns = 0; ns < 4; ns++)
                #pragma unroll
                for (int q = 0; q < 4; q++) c[mt][ns][q] = 0.f;

        const int arow = lane & 15;
        const int asel = (lane >> 4) * 8;
        #pragma unroll
        for (int kc = 0; kc < 8; kc++) {
            uint32_t a[2][4], b[2][4];
            #pragma unroll
            for (int mt = 0; mt < 2; mt++) {
                uint32_t off = (uint32_t)((wm * 32 + mt * 16 + arow) * WST +
                                          kc * 16 + asel) * 2;
                ldsm4(a[mt], sb + OFF_A + off);
            }
            #pragma unroll
            for (int g = 0; g < 2; g++) {
                uint32_t off = (uint32_t)((kc * 16 + arow) * WST +
                                          wn * 32 + g * 16 + asel) * 2;
                ldsm4t(b[g], sb + woff + off);
            }
            #pragma unroll
            for (int mt = 0; mt < 2; mt++)
                #pragma unroll
                for (int ns = 0; ns < 4; ns++)
                    mma_f16(c[mt][ns], a[mt], &b[ns >> 1][(ns & 1) * 2]);
        }
    };

    while (true) {
        if (tid == 0) s_tile = atomicAdd(ctr, 1);
        __syncthreads();
        const int tile = s_tile;
        if (tile >= NTILES) break;
        const int row0 = tile * 128;

        for (int i = tid; i < 2048; i += 512) {
            int r = i >> 4, cq = i & 15;
            int gr = row0 + r;
            uint4 p = make_uint4(0u, 0u, 0u, 0u);
            if (gr < NN) p = __ldg(hin + (size_t)gr * 16 + cq);
            *(uint2*)(smem + OFF_A + (uint32_t)(r * WST + cq * 8) * 2) =
                make_uint2(p.x, p.y);
            *(uint2*)(smem + OFF_A + (uint32_t)(r * WST + cq * 8 + 4) * 2) =
                make_uint2(p.z, p.w);
        }
        __syncthreads();

        gemm(OFF_W1);
        __syncthreads();

        #pragma unroll
        for (int mt = 0; mt < 2; mt++) {
            const int r0 = wm * 32 + mt * 16 + tg;
            #pragma unroll
            for (int ns = 0; ns < 4; ns++) {
                const int col = wn * 32 + ns * 8 + t4 * 2;
                const float bb0 = bs1f[col], bb1 = bs1f[col + 1];
                float v00 = fmaxf(c[mt][ns][0] + bb0, 0.f);
                float v01 = fmaxf(c[mt][ns][1] + bb1, 0.f);
                float v10 = fmaxf(c[mt][ns][2] + bb0, 0.f);
                float v11 = fmaxf(c[mt][ns][3] + bb1, 0.f);
                *(uint32_t*)(smem + OFF_A + (uint32_t)(r0 * WST + col) * 2) =
                    packh2(v00, v01);
                *(uint32_t*)(smem + OFF_A + (uint32_t)((r0 + 8) * WST + col) * 2) =
                    packh2(v10, v11);
            }
        }
        __syncthreads();

        gemm(OFF_W2);

        #pragma unroll
        for (int mt = 0; mt < 2; mt++) {
            const int r0 = row0 + wm * 32 + mt * 16 + tg;
            #pragma unroll
            for (int ns = 0; ns < 4; ns++) {
                const int col = wn * 32 + ns * 8 + t4 * 2;
                const float bb0 = bs2f[col], bb1 = bs2f[col + 1];
                float v00 = c[mt][ns][0] + bb0;
                float v01 = c[mt][ns][1] + bb1;
                float v10 = c[mt][ns][2] + bb0;
                float v11 = c[mt][ns][3] + bb1;
                if (inter) {
                    v00 = fmaxf(v00, 0.f); v01 = fmaxf(v01, 0.f);
                    v10 = fmaxf(v10, 0.f); v11 = fmaxf(v11, 0.f);
                    uint32_t* o16 = (uint32_t*)outp;
                    if (r0 < NN)
                        o16[(size_t)r0 * 64 + (col >> 1)] = packh2(v00, v01);
                    if (r0 + 8 < NN)
                        o16[(size_t)(r0 + 8) * 64 + (col >> 1)] = packh2(v10, v11);
                } else {
                    float* o32 = (float*)outp;
                    if (r0 < NN)
                        *(float2*)(o32 + (size_t)r0 * D + col) = make_float2(v00, v01);
                    if (r0 + 8 < NN)
                        *(float2*)(o32 + (size_t)(r0 + 8) * D + col) =
                            make_float2(v10, v11);
                }
            }
        }
    }
}

// ---------------------------------------------------------------------------
// launch
// ---------------------------------------------------------------------------
extern "C" void kernel_launch(void* const* d_in, const int* in_sizes, int n_in,
                              void* d_out, int out_size) {
    const float* x  = (const float*)d_in[0];
    const int*   ei = (const int*)d_in[1];
    const float* W1 = (const float*)d_in[2];
    const float* b1 = (const float*)d_in[3];
    const float* W2 = (const float*)d_in[4];
    const float* b2 = (const float*)d_in[5];

    const int* src = ei;
    const int* dst = ei + NE;

    uint4 *p_xa, *p_xb, *p_h;
    uint2 *p_w16;
    int *p_deg, *p_rows, *p_rowend, *p_cursor, *p_srcs, *p_misc;
    cudaGetSymbolAddress((void**)&p_xa,     g_xa);
    cudaGetSymbolAddress((void**)&p_xb,     g_xb);
    cudaGetSymbolAddress((void**)&p_h,      g_h);
    cudaGetSymbolAddress((void**)&p_w16,    g_w16);
    cudaGetSymbolAddress((void**)&p_deg,    g_deg);
    cudaGetSymbolAddress((void**)&p_rows,   g_rows);
    cudaGetSymbolAddress((void**)&p_rowend, g_rowend);
    cudaGetSymbolAddress((void**)&p_cursor, g_cursor);
    cudaGetSymbolAddress((void**)&p_srcs,   g_srcs);
    cudaGetSymbolAddress((void**)&p_misc,   g_misc);

    cudaFuncSetAttribute(mlp_mma_kernel, cudaFuncAttributeMaxDynamicSharedMemorySize,
                         SMEM_TOT);

    // ---- prep: launches 0-4 so the first gather is ncu launch #5 ----
    cudaMemsetAsync(p_deg, 0, NN * sizeof(int));                  // 0
    cudaMemsetAsync(p_misc, 0, 4 * sizeof(int));                  // 1
    hist_cvt_kernel<<<(NE + 255) / 256, 256>>>(                   // 2
        dst, p_deg, (const float4*)x, (uint2*)p_xa,
        (const float4*)W1, (const float4*)W2, p_w16);
    scan_kernel<<<NB_SCAN, 256>>>(p_deg, p_rows, p_rowend,        // 3
                                  p_cursor, p_misc + 3);
    fill_kernel<<<(NE + 255) / 256, 256>>>(src, dst, p_cursor, p_srcs);  // 4

    // ---- layers: fp16 activations; final layer writes fp32 d_out ----
    const uint4* lin[3] = {p_xa, p_xb, p_xa};
    void*       lout[3] = {p_xb, p_xa, d_out};

    for (int l = 0; l < NL; l++) {
        gather_mma_kernel<<<NN, 64>>>(lin[l], p_rows, p_rowend, p_srcs, p_h);
        mlp_mma_kernel<<<148, 512, SMEM_TOT>>>(
            p_h,
            p_w16 + (size_t)l * 4096, b1 + (size_t)l * D,
            p_w16 + (size_t)(NL + l) * 4096, b2 + (size_t)l * D,
            lout[l], (l < NL - 1) ? 1 : 0, p_misc + l);
    }
    (void)in_sizes; (void)n_in; (void)out_size;
}